// round 12
// baseline (speedup 1.0000x reference)
#include <cuda_runtime.h>
#include <cuda_bf16.h>

#define Bdim 64
#define Cdim 64
#define Tdim 128
#define Vdim 25
#define Rdim 8
#define TSdim 9
#define OUTdim 64
#define VV (Vdim*Vdim)          // 625
#define TV (Tdim*Vdim)          // 3200
#define XSTR 136                // T + TS-1 = 136 padded row
#define WKSTR 26                // Wk row stride (25 + 1 pad for 8B-aligned pairs)
#define WKTOT 5856              // padded Wk floats per (b,c): 9*25*26=5850 -> 5856 (16B mult)
#define PTILE 256               // kC p-tile

#define XDUP_BYTES (Vdim * XSTR * 8)          // 27200
#define WKS_BYTES  (WKTOT * 4)                // 23424
#define KB_SMEM    (XDUP_BYTES + WKS_BYTES)   // 50624

// scratch (device globals: no runtime allocation allowed)
__device__ float g_m[Bdim * Cdim * Vdim];                 // 0.41 MB  (time-mean)
__device__ float g_rel[Bdim * Rdim * VV];                 // 1.28 MB
__device__ float g_wk[(size_t)Bdim * Cdim * WKTOT];       // 95.9 MB  (prebuilt Wk)
__device__ float g_z[(size_t)Bdim * Cdim * Tdim * Vdim];  // 52.4 MB

// ---- f32x2 helpers (sm_103a packed FFMA path) ------------------------------
#define PACK_F32X2(out, lo, hi)                                        \
    asm("mov.b64 %0, {%1, %2};"                                        \
        : "=l"(out) : "r"(__float_as_uint(lo)), "r"(__float_as_uint(hi)))

#define UNPACK_F32X2(lo, hi, in)                                       \
    do { unsigned _ulo, _uhi;                                          \
         asm("mov.b64 {%0, %1}, %2;" : "=r"(_ulo), "=r"(_uhi) : "l"(in)); \
         lo = __uint_as_float(_ulo); hi = __uint_as_float(_uhi); } while (0)

#define FMA_F32X2(acc, a, b)                                           \
    asm("fma.rn.f32x2 %0, %1, %2, %0;" : "+l"(acc) : "l"(a), "l"(b))

// ---------------------------------------------------------------------------
// kA1: coalesced time-mean.  One block per (b,c).
// ---------------------------------------------------------------------------
__global__ __launch_bounds__(128) void kA1(const float* __restrict__ x) {
    const int c = blockIdx.x, b = blockIdx.y;
    const int tid = threadIdx.x;
    __shared__ __align__(16) float pl[Tdim * Vdim];   // 12.8 KB
    __shared__ float part[100];

    const float4* src = reinterpret_cast<const float4*>(
        x + ((size_t)b * Cdim + c) * TV);
    float4* dst = reinterpret_cast<float4*>(pl);
    for (int i = tid; i < TV / 4; i += 128) dst[i] = src[i];
    __syncthreads();

    if (tid < 100) {
        const int v = tid % Vdim, q = tid / Vdim;
        float s = 0.f;
#pragma unroll 8
        for (int j = 0; j < 32; j++) s += pl[(q * 32 + j) * Vdim + v];
        part[tid] = s;
    }
    __syncthreads();
    if (tid < Vdim) {
        float s = part[tid] + part[25 + tid] + part[50 + tid] + part[75 + tid];
        g_m[((size_t)b * Cdim + c) * Vdim + tid] = s * (1.0f / Tdim);
    }
}

// ---------------------------------------------------------------------------
// kA2: per-batch projections + tanh relation (tiny).
// ---------------------------------------------------------------------------
__global__ __launch_bounds__(256) void kA2(const float* __restrict__ W1,
                                           const float* __restrict__ b1,
                                           const float* __restrict__ W2,
                                           const float* __restrict__ b2) {
    const int b = blockIdx.x;
    const int tid = threadIdx.x;
    __shared__ float W1s[Rdim * Cdim], W2s[Rdim * Cdim];
    __shared__ float ms[Cdim * Vdim];
    __shared__ float x1s[Rdim * Vdim], x2s[Rdim * Vdim];

    for (int i = tid; i < Rdim * Cdim; i += 256) {
        W1s[i] = W1[i];
        W2s[i] = W2[i];
    }
    const float* mb = g_m + (size_t)b * Cdim * Vdim;
    for (int i = tid; i < Cdim * Vdim; i += 256) ms[i] = mb[i];
    __syncthreads();

    for (int item = tid; item < 2 * Rdim * Vdim; item += 256) {
        int which = item / (Rdim * Vdim);
        int rv = item % (Rdim * Vdim);
        int r = rv / Vdim, v = rv % Vdim;
        const float* Ws = which ? W2s : W1s;
        float s = which ? b2[r] : b1[r];
#pragma unroll
        for (int c = 0; c < Cdim; c++) s += Ws[r * Cdim + c] * ms[c * Vdim + v];
        if (which) x2s[rv] = s; else x1s[rv] = s;
    }
    __syncthreads();

    float* relb = g_rel + (size_t)b * Rdim * VV;
    for (int item = tid; item < Rdim * VV; item += 256) {
        int r = item / VV;
        int rem = item % VV;
        int i = rem / Vdim, j = rem % Vdim;
        relb[item] = tanhf(x1s[r * Vdim + i] - x2s[r * Vdim + j]);
    }
}

// ---------------------------------------------------------------------------
// kW: prebuild dynamic tap kernels for ALL (b,c) -> g_wk (padded layout).
//   g_wk[bc][(k*V+v)*WKSTR + i] = b4[c*TS+k] + A[v,i] + sum_r W4[..]*rel[b,r,v,i]
// Bandwidth-bound: writes 96 MB, reads rel from L2.
// ---------------------------------------------------------------------------
__global__ __launch_bounds__(128) void kW(const float* __restrict__ A,
                                          const float* __restrict__ W4,
                                          const float* __restrict__ b4) {
    const int c = blockIdx.x;
    const int b = blockIdx.y;
    const int tid = threadIdx.x;

    __shared__ float W4s[TSdim * Rdim];
    __shared__ float b4s[TSdim];
    if (tid < TSdim * Rdim) W4s[tid] = W4[(size_t)c * TSdim * Rdim + tid];
    if (tid < TSdim) b4s[tid] = b4[c * TSdim + tid];
    __syncthreads();

    float* wkb = g_wk + ((size_t)b * Cdim + c) * WKTOT;
    const float* relb = g_rel + (size_t)b * Rdim * VV;

    for (int vi = tid; vi < VV; vi += 128) {
        float rv[Rdim];
#pragma unroll
        for (int r = 0; r < Rdim; r++) rv[r] = relb[r * VV + vi];
        const float a = A[vi];
        const int v = vi / Vdim, i = vi % Vdim;
#pragma unroll
        for (int k = 0; k < TSdim; k++) {
            float s = b4s[k] + a;
#pragma unroll
            for (int r = 0; r < Rdim; r++) s += W4s[k * Rdim + r] * rv[r];
            wkb[(k * Vdim + v) * WKSTR + i] = s;
        }
    }
    // zero pad column + tail so the bulk copy in kB2 is branch-free
    for (int item = tid; item < TSdim * Vdim; item += 128)
        wkb[item * WKSTR + Vdim] = 0.f;
    for (int idx = TSdim * Vdim * WKSTR + tid; idx < WKTOT; idx += 128)
        wkb[idx] = 0.f;
}

// ---------------------------------------------------------------------------
// kB2: pure stage+compute temporal-graph conv (Wk prebuilt by kW).
//   z[t,i] = sum_{v,k} xs[v][t+k] * Wk[k][v][i]
// Thread = 8 t x 2 i.  wp loaded per-k (single u64 live) for low regs -> 4
// CTAs/SM (smem 49.4 KB x 4 fits; launch_bounds(224,4)).
// ---------------------------------------------------------------------------
__global__ __launch_bounds__(224, 4) void kB2(const float* __restrict__ x) {
    const int c = blockIdx.x;
    const int b = blockIdx.y;
    const int tid = threadIdx.x;

    extern __shared__ __align__(16) unsigned char smemB[];
    unsigned long long* xs2 = reinterpret_cast<unsigned long long*>(smemB); // 27.2 KB
    float* Wks = reinterpret_cast<float*>(smemB + XDUP_BYTES);              // 23.4 KB

    // stage Wk: plain float4 bulk copy (coalesced)
    {
        const float4* src = reinterpret_cast<const float4*>(
            g_wk + ((size_t)b * Cdim + c) * WKTOT);
        float4* dst = reinterpret_cast<float4*>(Wks);
        for (int i = tid; i < WKTOT / 4; i += 224) dst[i] = src[i];
    }

    // stage x tile pre-duplicated: xs2[v][tau] = (x,x); tau<8 causal pad = 0
    for (int i = tid; i < Vdim * 8; i += 224)
        xs2[(i / 8) * XSTR + (i % 8)] = 0ull;
    const float* xbc = x + ((size_t)b * Cdim + c) * TV;
    for (int item = tid; item < TV; item += 224) {
        int t = item / Vdim, v = item % Vdim;
        float val = xbc[item];
        unsigned long long d;
        PACK_F32X2(d, val, val);
        xs2[v * XSTR + 8 + t] = d;
    }
    __syncthreads();

    if (tid < 16 * 13) {
        const int tg = tid / 13;            // 0..15  -> t0 = 8*tg
        const int ip = tid % 13;            // 0..12  -> i0 = 2*ip
        const int i0 = 2 * ip;
        const int t0 = tg * 8;

        unsigned long long acc[8];
#pragma unroll
        for (int tt = 0; tt < 8; tt++) acc[tt] = 0ull;

#pragma unroll 1
        for (int v = 0; v < Vdim; v++) {
            unsigned long long xd[16];
            const unsigned long long* xp = &xs2[v * XSTR + t0];
#pragma unroll
            for (int j = 0; j < 16; j++) xd[j] = xp[j];

            const float* wkbase = &Wks[v * WKSTR + i0];
#pragma unroll
            for (int k = 0; k < TSdim; k++) {
                unsigned long long wp =
                    *reinterpret_cast<const unsigned long long*>(
                        wkbase + (size_t)k * Vdim * WKSTR);
#pragma unroll
                for (int tt = 0; tt < 8; tt++) FMA_F32X2(acc[tt], xd[tt + k], wp);
            }
        }

        float* zbc = g_z + ((size_t)b * Cdim + c) * TV;
#pragma unroll
        for (int tt = 0; tt < 8; tt++) {
            float lo, hi;
            UNPACK_F32X2(lo, hi, acc[tt]);
            zbc[(t0 + tt) * Vdim + i0] = lo;
            if (i0 + 1 < Vdim) zbc[(t0 + tt) * Vdim + i0 + 1] = hi;
        }
    }
}

// ---------------------------------------------------------------------------
// kC: conv3 register-tiled GEMM.  PTILE=256, thread = 8 o x 8 p.
// W3 pre-duplicated into smem as (w,w) u64 pairs at stage time -> hot loop
// has zero pack MOVs: 2 LDS.128 z + 4 LDS.128 w + 32 FFMA2 per c.
// ---------------------------------------------------------------------------
__global__ __launch_bounds__(256) void kC(const float* __restrict__ W3,
                                          const float* __restrict__ b3,
                                          float* __restrict__ out) {
    extern __shared__ __align__(16) float smemC[];
    float* zs = smemC;                                       // 64 x 256 (64 KB)
    unsigned long long* w3t2 =
        reinterpret_cast<unsigned long long*>(smemC + Cdim * PTILE); // 64x64 u64 (32 KB)

    const int b = blockIdx.y;
    const int p_base = blockIdx.x * PTILE;
    const int tid = threadIdx.x;
    const int og = tid >> 5;             // 0..7  -> o0 = og*8
    const int pg = tid & 31;             // 0..31 -> p0 = pg*8 (in tile)
    const int o0 = og * 8;
    const int pmax = TV - p_base;        // 256 (full) or 128 (last tile)

    // stage W3 transposed + pre-duplicated (coalesced read, smem scatter)
    for (int i = tid; i < Cdim * OUTdim; i += 256) {
        int o = i >> 6, c = i & 63;
        float wv = W3[i];
        unsigned long long d;
        PACK_F32X2(d, wv, wv);
        w3t2[c * OUTdim + o] = d;
    }
    // stage z tile (coalesced float4, zero-fill out-of-range)
    for (int i4 = tid; i4 < Cdim * (PTILE / 4); i4 += 256) {
        int c = i4 >> 6, j4 = i4 & 63;
        float4 v = make_float4(0.f, 0.f, 0.f, 0.f);
        if (j4 * 4 < pmax)
            v = *reinterpret_cast<const float4*>(
                g_z + ((size_t)b * Cdim + c) * TV + p_base + j4 * 4);
        *reinterpret_cast<float4*>(&zs[c * PTILE + j4 * 4]) = v;
    }
    __syncthreads();

    unsigned long long acc[8][4];
#pragma unroll
    for (int oo = 0; oo < 8; oo++)
#pragma unroll
        for (int q = 0; q < 4; q++) acc[oo][q] = 0ull;

#pragma unroll 4
    for (int c = 0; c < Cdim; c++) {
        const ulonglong2 za = *reinterpret_cast<const ulonglong2*>(&zs[c * PTILE + pg * 8]);
        const ulonglong2 zb2 = *reinterpret_cast<const ulonglong2*>(&zs[c * PTILE + pg * 8 + 4]);
        const ulonglong2 w01 = *reinterpret_cast<const ulonglong2*>(&w3t2[c * OUTdim + o0]);
        const ulonglong2 w23 = *reinterpret_cast<const ulonglong2*>(&w3t2[c * OUTdim + o0 + 2]);
        const ulonglong2 w45 = *reinterpret_cast<const ulonglong2*>(&w3t2[c * OUTdim + o0 + 4]);
        const ulonglong2 w67 = *reinterpret_cast<const ulonglong2*>(&w3t2[c * OUTdim + o0 + 6]);
        unsigned long long wd[8] = {w01.x, w01.y, w23.x, w23.y,
                                    w45.x, w45.y, w67.x, w67.y};
#pragma unroll
        for (int oo = 0; oo < 8; oo++) {
            FMA_F32X2(acc[oo][0], za.x,  wd[oo]);
            FMA_F32X2(acc[oo][1], za.y,  wd[oo]);
            FMA_F32X2(acc[oo][2], zb2.x, wd[oo]);
            FMA_F32X2(acc[oo][3], zb2.y, wd[oo]);
        }
    }

    if (pg * 8 < pmax) {
#pragma unroll
        for (int oo = 0; oo < 8; oo++) {
            const float bo = b3[o0 + oo];
            float r[8];
#pragma unroll
            for (int q = 0; q < 4; q++) {
                float lo, hi;
                UNPACK_F32X2(lo, hi, acc[oo][q]);
                r[2 * q] = lo + bo;
                r[2 * q + 1] = hi + bo;
            }
            float4* op4 = reinterpret_cast<float4*>(
                out + ((size_t)b * OUTdim + o0 + oo) * TV + p_base + pg * 8);
            op4[0] = make_float4(r[0], r[1], r[2], r[3]);
            op4[1] = make_float4(r[4], r[5], r[6], r[7]);
        }
    }
}

// ---------------------------------------------------------------------------
extern "C" void kernel_launch(void* const* d_in, const int* in_sizes, int n_in,
                              void* d_out, int out_size) {
    const float* x  = (const float*)d_in[0];
    const float* A  = (const float*)d_in[1];
    const float* W1 = (const float*)d_in[2];
    const float* b1 = (const float*)d_in[3];
    const float* W2 = (const float*)d_in[4];
    const float* b2 = (const float*)d_in[5];
    const float* W4 = (const float*)d_in[6];
    const float* b4 = (const float*)d_in[7];
    const float* W3 = (const float*)d_in[8];
    const float* b3 = (const float*)d_in[9];
    float* out = (float*)d_out;

    const int kc_smem = Cdim * PTILE * 4 + Cdim * OUTdim * 8; // 96 KB
    cudaFuncSetAttribute(kC, cudaFuncAttributeMaxDynamicSharedMemorySize, kc_smem);
    cudaFuncSetAttribute(kB2, cudaFuncAttributeMaxDynamicSharedMemorySize, KB_SMEM);

    kA1<<<dim3(Cdim, Bdim), 128>>>(x);
    kA2<<<Bdim, 256>>>(W1, b1, W2, b2);
    kW<<<dim3(Cdim, Bdim), 128>>>(A, W4, b4);
    kB2<<<dim3(Cdim, Bdim), 224, KB_SMEM>>>(x);
    kC<<<dim3((TV + PTILE - 1) / PTILE, Bdim), 256, kc_smem>>>(W3, b3, out);
}

// round 13
// speedup vs baseline: 1.1319x; 1.1319x over previous
#include <cuda_runtime.h>
#include <cuda_bf16.h>

#define Bdim 64
#define Cdim 64
#define Tdim 128
#define Vdim 25
#define Rdim 8
#define TSdim 9
#define OUTdim 64
#define VV (Vdim*Vdim)          // 625
#define TV (Tdim*Vdim)          // 3200
#define XSTR 136                // T + TS-1 = 136 padded row
#define WKSTR 28                // Wk row stride (25 + 3 pad -> 16B-aligned rows)
#define PTILE 256               // kC p-tile

#define XDUP_BYTES (Vdim * XSTR * 8)            // 27200
#define WKS_BYTES  (TSdim * Vdim * WKSTR * 4)   // 25200
#define KB_SMEM    (XDUP_BYTES + WKS_BYTES)     // 52400

// scratch (device globals: no runtime allocation allowed)
__device__ float g_m[Bdim * Cdim * Vdim];                 // 0.41 MB  (time-mean)
__device__ float g_rel[Bdim * Rdim * VV];                 // 1.28 MB
__device__ float g_z[(size_t)Bdim * Cdim * Tdim * Vdim];  // 52.4 MB

// ---- f32x2 helpers (sm_103a packed FFMA path) ------------------------------
#define PACK_F32X2(out, lo, hi)                                        \
    asm("mov.b64 %0, {%1, %2};"                                        \
        : "=l"(out) : "r"(__float_as_uint(lo)), "r"(__float_as_uint(hi)))

#define UNPACK_F32X2(lo, hi, in)                                       \
    do { unsigned _ulo, _uhi;                                          \
         asm("mov.b64 {%0, %1}, %2;" : "=r"(_ulo), "=r"(_uhi) : "l"(in)); \
         lo = __uint_as_float(_ulo); hi = __uint_as_float(_uhi); } while (0)

#define FMA_F32X2(acc, a, b)                                           \
    asm("fma.rn.f32x2 %0, %1, %2, %0;" : "+l"(acc) : "l"(a), "l"(b))

// ---------------------------------------------------------------------------
// kA1: coalesced time-mean.  One block per (b,c).
// ---------------------------------------------------------------------------
__global__ __launch_bounds__(128) void kA1(const float* __restrict__ x) {
    const int c = blockIdx.x, b = blockIdx.y;
    const int tid = threadIdx.x;
    __shared__ __align__(16) float pl[Tdim * Vdim];   // 12.8 KB
    __shared__ float part[100];

    const float4* src = reinterpret_cast<const float4*>(
        x + ((size_t)b * Cdim + c) * TV);
    float4* dst = reinterpret_cast<float4*>(pl);
    for (int i = tid; i < TV / 4; i += 128) dst[i] = src[i];
    __syncthreads();

    if (tid < 100) {
        const int v = tid % Vdim, q = tid / Vdim;
        float s = 0.f;
#pragma unroll 8
        for (int j = 0; j < 32; j++) s += pl[(q * 32 + j) * Vdim + v];
        part[tid] = s;
    }
    __syncthreads();
    if (tid < Vdim) {
        float s = part[tid] + part[25 + tid] + part[50 + tid] + part[75 + tid];
        g_m[((size_t)b * Cdim + c) * Vdim + tid] = s * (1.0f / Tdim);
    }
}

// ---------------------------------------------------------------------------
// kA2: per-batch projections + tanh relation (tiny).
// ---------------------------------------------------------------------------
__global__ __launch_bounds__(256) void kA2(const float* __restrict__ W1,
                                           const float* __restrict__ b1,
                                           const float* __restrict__ W2,
                                           const float* __restrict__ b2) {
    const int b = blockIdx.x;
    const int tid = threadIdx.x;
    __shared__ float W1s[Rdim * Cdim], W2s[Rdim * Cdim];
    __shared__ float ms[Cdim * Vdim];
    __shared__ float x1s[Rdim * Vdim], x2s[Rdim * Vdim];

    for (int i = tid; i < Rdim * Cdim; i += 256) {
        W1s[i] = W1[i];
        W2s[i] = W2[i];
    }
    const float* mb = g_m + (size_t)b * Cdim * Vdim;
    for (int i = tid; i < Cdim * Vdim; i += 256) ms[i] = mb[i];
    __syncthreads();

    for (int item = tid; item < 2 * Rdim * Vdim; item += 256) {
        int which = item / (Rdim * Vdim);
        int rv = item % (Rdim * Vdim);
        int r = rv / Vdim, v = rv % Vdim;
        const float* Ws = which ? W2s : W1s;
        float s = which ? b2[r] : b1[r];
#pragma unroll
        for (int c = 0; c < Cdim; c++) s += Ws[r * Cdim + c] * ms[c * Vdim + v];
        if (which) x2s[rv] = s; else x1s[rv] = s;
    }
    __syncthreads();

    float* relb = g_rel + (size_t)b * Rdim * VV;
    for (int item = tid; item < Rdim * VV; item += 256) {
        int r = item / VV;
        int rem = item % VV;
        int i = rem / Vdim, j = rem % Vdim;
        relb[item] = tanhf(x1s[r * Vdim + i] - x2s[r * Vdim + j]);
    }
}

// ---------------------------------------------------------------------------
// kB: per-(b,c) fused dynamic-tap conv, f32x2 over i, 8t x 4i register tile.
//   Wk[k][v][i] = b4[c*TS+k] + A[v,i] + sum_r W4[c*TS+k,r]*rel[b,r,v,i]
//   z[t,i]      = sum_{v,k} xs[v][t+k] * Wk[k][v][i]
// Per v per thread: 16 broadcast LDS.64 (dup'd x) + 9 LDS.128 (4 wk values)
// feeding 144 FFMA2.  Workers: 16 tg x 7 ip = 112 of 128 threads.
// ---------------------------------------------------------------------------
__global__ __launch_bounds__(128, 4) void kB(const float* __restrict__ x,
                                             const float* __restrict__ A,
                                             const float* __restrict__ W4,
                                             const float* __restrict__ b4) {
    const int c = blockIdx.x;
    const int b = blockIdx.y;
    const int tid = threadIdx.x;

    extern __shared__ __align__(16) unsigned char smemB[];
    unsigned long long* xs2 = reinterpret_cast<unsigned long long*>(smemB); // 27.2 KB
    float* Wks = reinterpret_cast<float*>(smemB + XDUP_BYTES);              // 25.2 KB
    __shared__ float W4s[TSdim * Rdim];
    __shared__ float b4s[TSdim];

    if (tid < TSdim * Rdim) W4s[tid] = W4[(size_t)c * TSdim * Rdim + tid];
    if (tid < TSdim) b4s[tid] = b4[c * TSdim + tid];
    __syncthreads();

    // build Wk: one rel-row read per vi, all 9 taps written
    const float* relb = g_rel + (size_t)b * Rdim * VV;
    for (int vi = tid; vi < VV; vi += 128) {
        float rv[Rdim];
#pragma unroll
        for (int r = 0; r < Rdim; r++) rv[r] = relb[r * VV + vi];
        const float a = A[vi];
        const int v = vi / Vdim, i = vi % Vdim;
        float* wout = &Wks[v * WKSTR + i];
#pragma unroll
        for (int k = 0; k < TSdim; k++) {
            float s = b4s[k] + a;
#pragma unroll
            for (int r = 0; r < Rdim; r++) s += W4s[k * Rdim + r] * rv[r];
            wout[(size_t)k * Vdim * WKSTR] = s;
        }
    }
    // zero the 3 pad columns of every row
    for (int item = tid; item < TSdim * Vdim * 3; item += 128) {
        int row = item / 3, pcol = item % 3;
        Wks[row * WKSTR + Vdim + pcol] = 0.f;
    }

    // stage x tile pre-duplicated: xs2[v][tau] = (x,x); tau<8 causal pad = 0
    for (int i = tid; i < Vdim * 8; i += 128)
        xs2[(i / 8) * XSTR + (i % 8)] = 0ull;
    const float* xbc = x + ((size_t)b * Cdim + c) * TV;
    for (int item = tid; item < TV; item += 128) {
        int t = item / Vdim, v = item % Vdim;
        float val = xbc[item];
        unsigned long long d;
        PACK_F32X2(d, val, val);
        xs2[v * XSTR + 8 + t] = d;
    }
    __syncthreads();

    if (tid < 16 * 7) {
        const int tg = tid / 7;             // 0..15 -> t0 = 8*tg
        const int ip = tid % 7;             // 0..6  -> i0 = 4*ip (24..27 partly pad)
        const int i0 = 4 * ip;
        const int t0 = tg * 8;

        unsigned long long acc[8][2];
#pragma unroll
        for (int tt = 0; tt < 8; tt++) { acc[tt][0] = 0ull; acc[tt][1] = 0ull; }

#pragma unroll 1
        for (int v = 0; v < Vdim; v++) {
            unsigned long long xd[16];
            const unsigned long long* xp = &xs2[v * XSTR + t0];
#pragma unroll
            for (int j = 0; j < 16; j++) xd[j] = xp[j];

            const float* wkbase = &Wks[v * WKSTR + i0];
#pragma unroll
            for (int k = 0; k < TSdim; k++) {
                const ulonglong2 wq = *reinterpret_cast<const ulonglong2*>(
                    wkbase + (size_t)k * Vdim * WKSTR);
#pragma unroll
                for (int tt = 0; tt < 8; tt++) {
                    FMA_F32X2(acc[tt][0], xd[tt + k], wq.x);
                    FMA_F32X2(acc[tt][1], xd[tt + k], wq.y);
                }
            }
        }

        float* zbc = g_z + ((size_t)b * Cdim + c) * TV;
#pragma unroll
        for (int tt = 0; tt < 8; tt++) {
            float r0, r1, r2, r3;
            UNPACK_F32X2(r0, r1, acc[tt][0]);
            UNPACK_F32X2(r2, r3, acc[tt][1]);
            float* zr = &zbc[(t0 + tt) * Vdim + i0];
            zr[0] = r0;
            if (i0 + 1 < Vdim) zr[1] = r1;
            if (i0 + 2 < Vdim) zr[2] = r2;
            if (i0 + 3 < Vdim) zr[3] = r3;
        }
    }
}

// ---------------------------------------------------------------------------
// kC: conv3 register-tiled GEMM (proven config, ~74 us).
// PTILE=256, thread = 8 o x 8 p, W3 pre-duplicated u64 in smem.
// ---------------------------------------------------------------------------
__global__ __launch_bounds__(256) void kC(const float* __restrict__ W3,
                                          const float* __restrict__ b3,
                                          float* __restrict__ out) {
    extern __shared__ __align__(16) float smemC[];
    float* zs = smemC;                                       // 64 x 256 (64 KB)
    unsigned long long* w3t2 =
        reinterpret_cast<unsigned long long*>(smemC + Cdim * PTILE); // 32 KB

    const int b = blockIdx.y;
    const int p_base = blockIdx.x * PTILE;
    const int tid = threadIdx.x;
    const int og = tid >> 5;             // 0..7  -> o0 = og*8
    const int pg = tid & 31;             // 0..31 -> p0 = pg*8 (in tile)
    const int o0 = og * 8;
    const int pmax = TV - p_base;        // 256 (full) or 128 (last tile)

    for (int i = tid; i < Cdim * OUTdim; i += 256) {
        int o = i >> 6, c = i & 63;
        float wv = W3[i];
        unsigned long long d;
        PACK_F32X2(d, wv, wv);
        w3t2[c * OUTdim + o] = d;
    }
    for (int i4 = tid; i4 < Cdim * (PTILE / 4); i4 += 256) {
        int c = i4 >> 6, j4 = i4 & 63;
        float4 v = make_float4(0.f, 0.f, 0.f, 0.f);
        if (j4 * 4 < pmax)
            v = *reinterpret_cast<const float4*>(
                g_z + ((size_t)b * Cdim + c) * TV + p_base + j4 * 4);
        *reinterpret_cast<float4*>(&zs[c * PTILE + j4 * 4]) = v;
    }
    __syncthreads();

    unsigned long long acc[8][4];
#pragma unroll
    for (int oo = 0; oo < 8; oo++)
#pragma unroll
        for (int q = 0; q < 4; q++) acc[oo][q] = 0ull;

#pragma unroll 4
    for (int c = 0; c < Cdim; c++) {
        const ulonglong2 za = *reinterpret_cast<const ulonglong2*>(&zs[c * PTILE + pg * 8]);
        const ulonglong2 zb2 = *reinterpret_cast<const ulonglong2*>(&zs[c * PTILE + pg * 8 + 4]);
        const ulonglong2 w01 = *reinterpret_cast<const ulonglong2*>(&w3t2[c * OUTdim + o0]);
        const ulonglong2 w23 = *reinterpret_cast<const ulonglong2*>(&w3t2[c * OUTdim + o0 + 2]);
        const ulonglong2 w45 = *reinterpret_cast<const ulonglong2*>(&w3t2[c * OUTdim + o0 + 4]);
        const ulonglong2 w67 = *reinterpret_cast<const ulonglong2*>(&w3t2[c * OUTdim + o0 + 6]);
        unsigned long long wd[8] = {w01.x, w01.y, w23.x, w23.y,
                                    w45.x, w45.y, w67.x, w67.y};
#pragma unroll
        for (int oo = 0; oo < 8; oo++) {
            FMA_F32X2(acc[oo][0], za.x,  wd[oo]);
            FMA_F32X2(acc[oo][1], za.y,  wd[oo]);
            FMA_F32X2(acc[oo][2], zb2.x, wd[oo]);
            FMA_F32X2(acc[oo][3], zb2.y, wd[oo]);
        }
    }

    if (pg * 8 < pmax) {
#pragma unroll
        for (int oo = 0; oo < 8; oo++) {
            const float bo = b3[o0 + oo];
            float r[8];
#pragma unroll
            for (int q = 0; q < 4; q++) {
                float lo, hi;
                UNPACK_F32X2(lo, hi, acc[oo][q]);
                r[2 * q] = lo + bo;
                r[2 * q + 1] = hi + bo;
            }
            float4* op4 = reinterpret_cast<float4*>(
                out + ((size_t)b * OUTdim + o0 + oo) * TV + p_base + pg * 8);
            op4[0] = make_float4(r[0], r[1], r[2], r[3]);
            op4[1] = make_float4(r[4], r[5], r[6], r[7]);
        }
    }
}

// ---------------------------------------------------------------------------
extern "C" void kernel_launch(void* const* d_in, const int* in_sizes, int n_in,
                              void* d_out, int out_size) {
    const float* x  = (const float*)d_in[0];
    const float* A  = (const float*)d_in[1];
    const float* W1 = (const float*)d_in[2];
    const float* b1 = (const float*)d_in[3];
    const float* W2 = (const float*)d_in[4];
    const float* b2 = (const float*)d_in[5];
    const float* W4 = (const float*)d_in[6];
    const float* b4 = (const float*)d_in[7];
    const float* W3 = (const float*)d_in[8];
    const float* b3 = (const float*)d_in[9];
    float* out = (float*)d_out;

    const int kc_smem = Cdim * PTILE * 4 + Cdim * OUTdim * 8; // 96 KB
    cudaFuncSetAttribute(kC, cudaFuncAttributeMaxDynamicSharedMemorySize, kc_smem);
    cudaFuncSetAttribute(kB, cudaFuncAttributeMaxDynamicSharedMemorySize, KB_SMEM);

    kA1<<<dim3(Cdim, Bdim), 128>>>(x);
    kA2<<<Bdim, 256>>>(W1, b1, W2, b2);
    kB<<<dim3(Cdim, Bdim), 128, KB_SMEM>>>(x, A, W4, b4);
    kC<<<dim3((TV + PTILE - 1) / PTILE, Bdim), 256, kc_smem>>>(W3, b3, out);
}